// round 2
// baseline (speedup 1.0000x reference)
#include <cuda_runtime.h>
#include <cstdint>

#define L_Q   4096
#define L_CTX 4097
#define C_DIM 320
#define N_HEADS 8
#define DHEAD 40
#define BQ 64
#define BK 64

// ---------------- device scratch (no allocations allowed) ----------------
__device__ float g_ctx[L_CTX * C_DIM];           // context = [reg; x]  (4097 x 320)
__device__ float g_q[N_HEADS * L_Q * DHEAD];     // [h][s][d]
__device__ float g_k[N_HEADS * L_CTX * DHEAD];   // [h][s][d]
__device__ float g_v[N_HEADS * L_CTX * DHEAD];   // [h][s][d]
__device__ float g_o[L_Q * C_DIM];               // merged-head attention output
__device__ int   g_mask_is_u8;                   // 1 if mask stored as bytes, 0 if int32

// ---------------- kernel 0: detect mask dtype ----------------
// int32 {0,1}: ~512 nonzero bytes in first 4096; uint8 {0,1}: ~2048.
__global__ void detect_mask_kernel(const unsigned char* __restrict__ mask) {
    __shared__ int cnt[256];
    int tid = threadIdx.x;
    int c = 0;
    for (int i = tid; i < 4096; i += 256) c += (mask[i] != 0);
    cnt[tid] = c;
    __syncthreads();
    for (int s = 128; s; s >>= 1) {
        if (tid < s) cnt[tid] += cnt[tid + s];
        __syncthreads();
    }
    if (tid == 0) g_mask_is_u8 = (cnt[0] > 1024) ? 1 : 0;
}

// ---------------- kernel 1: build context ----------------
// features (1,16,320,16,16) -> x (4096,320); context row0 = reg_tokens
__global__ void build_ctx_kernel(const float* __restrict__ feat,
                                 const float* __restrict__ reg) {
    int b = blockIdx.x;
    int x = threadIdx.x;  // 0..255 = hh*16+ww
    if (b == 16 * C_DIM) {
        for (int c = x; c < C_DIM; c += 256) g_ctx[c] = reg[c];
        return;
    }
    int t = b / C_DIM;
    int c = b - t * C_DIM;
    float v = feat[(t * C_DIM + c) * 256 + x];
    g_ctx[(size_t)(1 + t * 256 + x) * C_DIM + c] = v;
}

// ---------------- kernel 2: fused QKV projection GEMM ----------------
__global__ void qkv_gemm_kernel(const float* __restrict__ Wq,
                                const float* __restrict__ Wk,
                                const float* __restrict__ Wv) {
    __shared__ float sA[16][68];  // [kk][m]
    __shared__ float sB[16][68];  // [kk][n]

    int z = blockIdx.z;
    const float* W = (z == 0) ? Wq : ((z == 1) ? Wk : Wv);
    int rows = (z == 0) ? L_Q : L_CTX;
    const float* A = g_ctx + ((z == 0) ? C_DIM : 0);
    float* out = (z == 0) ? g_q : ((z == 1) ? g_k : g_v);

    int row0 = blockIdx.x * 64;
    int n0   = blockIdx.y * 64;
    int tid = threadIdx.x;
    int ty = tid >> 4, tx = tid & 15;

    float acc[4][4] = {};

    int lam = tid >> 2;          // 0..63  (A tile row)
    int lak = (tid & 3) * 4;     // k group
    int lbk = tid >> 4;          // 0..15  (B tile k)
    int lbn = (tid & 15) * 4;    // n group

    for (int k0 = 0; k0 < C_DIM; k0 += 16) {
        float4 av = make_float4(0.f, 0.f, 0.f, 0.f);
        if (row0 + lam < rows)
            av = *(const float4*)&A[(size_t)(row0 + lam) * C_DIM + k0 + lak];
        sA[lak + 0][lam] = av.x;
        sA[lak + 1][lam] = av.y;
        sA[lak + 2][lam] = av.z;
        sA[lak + 3][lam] = av.w;
        *(float4*)&sB[lbk][lbn] =
            *(const float4*)&W[(size_t)(k0 + lbk) * C_DIM + n0 + lbn];
        __syncthreads();
#pragma unroll
        for (int kk = 0; kk < 16; kk++) {
            float4 a4 = *(float4*)&sA[kk][ty * 4];
            float4 b4 = *(float4*)&sB[kk][tx * 4];
            float avv[4] = {a4.x, a4.y, a4.z, a4.w};
            float bvv[4] = {b4.x, b4.y, b4.z, b4.w};
#pragma unroll
            for (int i = 0; i < 4; i++)
#pragma unroll
                for (int j = 0; j < 4; j++) acc[i][j] += avv[i] * bvv[j];
        }
        __syncthreads();
    }

    float scale = (z == 0) ? rsqrtf((float)DHEAD) : 1.0f;
#pragma unroll
    for (int i = 0; i < 4; i++) {
        int s = row0 + ty * 4 + i;
        if (s >= rows) continue;
#pragma unroll
        for (int j = 0; j < 4; j++) {
            int jc = n0 + tx * 4 + j;
            int h = jc / DHEAD;
            int d = jc - h * DHEAD;
            out[((size_t)h * rows + s) * DHEAD + d] = acc[i][j] * scale;
        }
    }
}

// ---------------- kernel 3: flash attention (fp32, online softmax) ----------------
__global__ void flash_kernel(const unsigned char* __restrict__ mask) {
    extern __shared__ float sm[];
    float* sQT = sm;                 // [40][64]  Q^T
    float* sKT = sm + 2560;          // [40][64]  K^T
    float* sV  = sm + 5120;          // [64][40]
    float* sP  = sm + 7680;          // [64][65]
    float* sm_m = sm + 11840;        // [64]
    float* sm_l = sm + 11904;        // [64]
    float* sm_c = sm + 11968;        // [64]
    unsigned char* sM = (unsigned char*)(sm + 12032);  // [64][64] bytes

    int qb = blockIdx.x, h = blockIdx.y;
    int q0 = qb * BQ;
    int tid = threadIdx.x;
    int mask_u8 = g_mask_is_u8;

    const float* qg = g_q + (size_t)h * L_Q * DHEAD;
    const float* kg = g_k + (size_t)h * L_CTX * DHEAD;
    const float* vg = g_v + (size_t)h * L_CTX * DHEAD;

    // load Q tile transposed
    for (int idx = tid; idx < BQ * DHEAD; idx += 256) {
        int s = idx / DHEAD, d = idx - s * DHEAD;
        sQT[d * 64 + s] = qg[(size_t)(q0 + s) * DHEAD + d];
    }
    __syncthreads();

    // init stats with register-token contribution (always visible)
    if (tid < 64) {
        float s0 = 0.f;
#pragma unroll
        for (int d = 0; d < DHEAD; d++) s0 += sQT[d * 64 + tid] * kg[d];
        sm_m[tid] = s0;
        sm_l[tid] = 1.0f;
    }

    // PV mapping: 160 active threads, each owns 4 q-rows x 4 dims
    bool pv = (tid < 160);
    int qgp = tid / 10;          // 0..15
    int dgp = tid - qgp * 10;    // 0..9
    float o[4][4] = {};
    if (pv) {
#pragma unroll
        for (int j = 0; j < 4; j++) {
            float vr = vg[dgp * 4 + j];   // v of register token
            o[0][j] = vr; o[1][j] = vr; o[2][j] = vr; o[3][j] = vr;
        }
    }

    int ty = tid >> 4, tx = tid & 15;   // S-phase mapping: 4q x 4k per thread

    for (int t = 0; t < 64; t++) {
        int k0 = t * 64;
        __syncthreads();
        // load K tile (transposed) + V tile
        for (int idx = tid; idx < BK * DHEAD; idx += 256) {
            int s = idx / DHEAD, d = idx - s * DHEAD;
            size_t gofs = (size_t)(1 + k0 + s) * DHEAD + d;
            sKT[d * 64 + s] = kg[gofs];
            sV[s * 40 + d]  = vg[gofs];
        }
        {   // mask tile: ctx key j = 1+k0+kk -> mask column k0+kk (aligned)
            int r = tid >> 2;
            int cg = (tid & 3) * 16;
            if (mask_u8) {
                *(uint4*)&sM[r * 64 + cg] =
                    *(const uint4*)&mask[(size_t)(q0 + r) * 4096 + k0 + cg];
            } else {
                const int* mi = (const int*)mask;
                const int* row = &mi[(size_t)(q0 + r) * 4096 + k0 + cg];
#pragma unroll
                for (int j = 0; j < 16; j += 4) {
                    int4 w = *(const int4*)&row[j];
                    sM[r * 64 + cg + j + 0] = (unsigned char)(w.x != 0);
                    sM[r * 64 + cg + j + 1] = (unsigned char)(w.y != 0);
                    sM[r * 64 + cg + j + 2] = (unsigned char)(w.z != 0);
                    sM[r * 64 + cg + j + 3] = (unsigned char)(w.w != 0);
                }
            }
        }
        __syncthreads();

        // ---- S = Q K^T (scale pre-folded into Q) ----
        float rs[4][4] = {};
#pragma unroll 10
        for (int d = 0; d < DHEAD; d++) {
            float4 a = *(float4*)&sQT[d * 64 + ty * 4];
            float4 b = *(float4*)&sKT[d * 64 + tx * 4];
            float avv[4] = {a.x, a.y, a.z, a.w};
            float bvv[4] = {b.x, b.y, b.z, b.w};
#pragma unroll
            for (int i = 0; i < 4; i++)
#pragma unroll
                for (int j = 0; j < 4; j++) rs[i][j] += avv[i] * bvv[j];
        }

        // ---- mask + online softmax (row = 16 lanes, shfl width 16) ----
#pragma unroll
        for (int i = 0; i < 4; i++) {
            int q = ty * 4 + i;
            uchar4 mm = *(uchar4*)&sM[q * 64 + tx * 4];
            float s0v = mm.x ? rs[i][0] : -1e30f;
            float s1v = mm.y ? rs[i][1] : -1e30f;
            float s2v = mm.z ? rs[i][2] : -1e30f;
            float s3v = mm.w ? rs[i][3] : -1e30f;
            float lm = fmaxf(fmaxf(s0v, s1v), fmaxf(s2v, s3v));
#pragma unroll
            for (int off = 8; off; off >>= 1)
                lm = fmaxf(lm, __shfl_xor_sync(0xffffffffu, lm, off));
            float mo = sm_m[q];
            float mn = fmaxf(mo, lm);
            float p0 = __expf(s0v - mn);
            float p1 = __expf(s1v - mn);
            float p2 = __expf(s2v - mn);
            float p3 = __expf(s3v - mn);
            float rsum = (p0 + p1) + (p2 + p3);
#pragma unroll
            for (int off = 8; off; off >>= 1)
                rsum += __shfl_xor_sync(0xffffffffu, rsum, off);
            if (tx == 0) {
                float corr = __expf(mo - mn);
                sm_m[q] = mn;
                sm_l[q] = sm_l[q] * corr + rsum;
                sm_c[q] = corr;
            }
            sP[q * 65 + tx * 4 + 0] = p0;
            sP[q * 65 + tx * 4 + 1] = p1;
            sP[q * 65 + tx * 4 + 2] = p2;
            sP[q * 65 + tx * 4 + 3] = p3;
        }
        __syncthreads();

        // ---- O = O*corr + P @ V ----
        if (pv) {
            int qr = qgp * 4;
            float c0 = sm_c[qr + 0], c1 = sm_c[qr + 1];
            float c2 = sm_c[qr + 2], c3 = sm_c[qr + 3];
#pragma unroll
            for (int j = 0; j < 4; j++) {
                o[0][j] *= c0; o[1][j] *= c1; o[2][j] *= c2; o[3][j] *= c3;
            }
#pragma unroll 4
            for (int k = 0; k < 64; k++) {
                float4 vv = *(float4*)&sV[k * 40 + dgp * 4];
                float vvv[4] = {vv.x, vv.y, vv.z, vv.w};
                float p[4];
                p[0] = sP[(qr + 0) * 65 + k];
                p[1] = sP[(qr + 1) * 65 + k];
                p[2] = sP[(qr + 2) * 65 + k];
                p[3] = sP[(qr + 3) * 65 + k];
#pragma unroll
                for (int i = 0; i < 4; i++)
#pragma unroll
                    for (int j = 0; j < 4; j++) o[i][j] += p[i] * vvv[j];
            }
        }
    }

    // ---- epilogue: normalize + write merged-head layout ----
    if (pv) {
#pragma unroll
        for (int i = 0; i < 4; i++) {
            int q = qgp * 4 + i;
            float inv = 1.0f / sm_l[q];
            float4 r = make_float4(o[i][0] * inv, o[i][1] * inv,
                                   o[i][2] * inv, o[i][3] * inv);
            *(float4*)&g_o[(size_t)(q0 + q) * C_DIM + h * DHEAD + dgp * 4] = r;
        }
    }
}

// ---------------- kernel 4: output projection + bias + permute ----------------
__global__ void out_gemm_kernel(const float* __restrict__ Wo,
                                const float* __restrict__ bo,
                                float* __restrict__ out) {
    __shared__ float sA[16][68];
    __shared__ float sB[16][68];

    int row0 = blockIdx.x * 64;
    int n0   = blockIdx.y * 64;
    int tid = threadIdx.x;
    int ty = tid >> 4, tx = tid & 15;
    float acc[4][4] = {};

    int lam = tid >> 2;
    int lak = (tid & 3) * 4;
    int lbk = tid >> 4;
    int lbn = (tid & 15) * 4;

    for (int k0 = 0; k0 < C_DIM; k0 += 16) {
        float4 av = *(const float4*)&g_o[(size_t)(row0 + lam) * C_DIM + k0 + lak];
        sA[lak + 0][lam] = av.x;
        sA[lak + 1][lam] = av.y;
        sA[lak + 2][lam] = av.z;
        sA[lak + 3][lam] = av.w;
        *(float4*)&sB[lbk][lbn] =
            *(const float4*)&Wo[(size_t)(k0 + lbk) * C_DIM + n0 + lbn];
        __syncthreads();
#pragma unroll
        for (int kk = 0; kk < 16; kk++) {
            float4 a4 = *(float4*)&sA[kk][ty * 4];
            float4 b4 = *(float4*)&sB[kk][tx * 4];
            float avv[4] = {a4.x, a4.y, a4.z, a4.w};
            float bvv[4] = {b4.x, b4.y, b4.z, b4.w};
#pragma unroll
            for (int i = 0; i < 4; i++)
#pragma unroll
                for (int j = 0; j < 4; j++) acc[i][j] += avv[i] * bvv[j];
        }
        __syncthreads();
    }

#pragma unroll
    for (int i = 0; i < 4; i++) {
        int s = row0 + ty * 4 + i;
        int r = (s & 255) * 16 + (s >> 8);   // (B H W) T permutation
#pragma unroll
        for (int j = 0; j < 4; j++) {
            int c = n0 + tx * 4 + j;
            out[(size_t)r * C_DIM + c] = acc[i][j] + bo[c];
        }
    }
}

// ---------------- launch ----------------
extern "C" void kernel_launch(void* const* d_in, const int* in_sizes, int n_in,
                              void* d_out, int out_size) {
    const float* feat         = (const float*)d_in[0];
    const unsigned char* mask = (const unsigned char*)d_in[1];
    const float* Wq           = (const float*)d_in[2];
    const float* Wk           = (const float*)d_in[3];
    const float* Wv           = (const float*)d_in[4];
    const float* reg          = (const float*)d_in[5];
    const float* Wo           = (const float*)d_in[6];
    const float* bo           = (const float*)d_in[7];
    float* out                = (float*)d_out;

    (void)in_sizes; (void)n_in; (void)out_size;

    detect_mask_kernel<<<1, 256>>>(mask);
    build_ctx_kernel<<<16 * C_DIM + 1, 256>>>(feat, reg);
    qkv_gemm_kernel<<<dim3(65, 5, 3), 256>>>(Wq, Wk, Wv);

    const int FLASH_SMEM = 12032 * 4 + 64 * 64;  // 52224 bytes
    cudaFuncSetAttribute(flash_kernel,
                         cudaFuncAttributeMaxDynamicSharedMemorySize, FLASH_SMEM);
    flash_kernel<<<dim3(64, N_HEADS), 256, FLASH_SMEM>>>(mask);

    out_gemm_kernel<<<dim3(64, 5), 256>>>(Wo, bo, out);
}

// round 3
// speedup vs baseline: 3.7404x; 3.7404x over previous
#include <cuda_runtime.h>
#include <cuda_fp16.h>
#include <cstdint>

#define L_Q   4096
#define L_CTX 4097
#define C_DIM 320
#define N_HEADS 8
#define DHEAD 40
#define DPAD  48

// ---------------- device scratch (no allocations allowed) ----------------
__device__ float  g_ctx[L_CTX * C_DIM];             // context fp32 (for projections)
__device__ __half g_q[(size_t)N_HEADS * L_Q * DPAD];    // fp16, d 40..47 stay zero
__device__ __half g_k[(size_t)N_HEADS * L_CTX * DPAD];
__device__ __half g_v[(size_t)N_HEADS * L_CTX * DPAD];
__device__ float  g_o[L_Q * C_DIM];                 // merged-head attention output
__device__ unsigned g_mbits[L_Q * 128];             // packed mask bits: 4096 x 4096 bits
__device__ int    g_mask_is_u8;

// ---------------- mma / ldmatrix helpers ----------------
__device__ __forceinline__ void mma16816(float* d, const uint32_t* a, const uint32_t* b) {
    asm volatile(
        "mma.sync.aligned.m16n8k16.row.col.f32.f16.f16.f32 "
        "{%0,%1,%2,%3}, {%4,%5,%6,%7}, {%8,%9}, {%0,%1,%2,%3};"
        : "+f"(d[0]), "+f"(d[1]), "+f"(d[2]), "+f"(d[3])
        : "r"(a[0]), "r"(a[1]), "r"(a[2]), "r"(a[3]), "r"(b[0]), "r"(b[1]));
}
__device__ __forceinline__ void ldsm4(uint32_t* r, uint32_t saddr) {
    asm volatile("ldmatrix.sync.aligned.m8n8.x4.shared.b16 {%0,%1,%2,%3}, [%4];"
                 : "=r"(r[0]), "=r"(r[1]), "=r"(r[2]), "=r"(r[3]) : "r"(saddr));
}
__device__ __forceinline__ void ldsm2t(uint32_t* r, uint32_t saddr) {
    asm volatile("ldmatrix.sync.aligned.m8n8.x2.trans.shared.b16 {%0,%1}, [%2];"
                 : "=r"(r[0]), "=r"(r[1]) : "r"(saddr));
}
__device__ __forceinline__ uint32_t pack_half2(float lo, float hi) {
    __half2 h = __floats2half2_rn(lo, hi);
    return *(uint32_t*)&h;
}

// ---------------- kernel 0: detect mask dtype ----------------
__global__ void detect_mask_kernel(const unsigned char* __restrict__ mask) {
    __shared__ int cnt[256];
    int tid = threadIdx.x;
    int c = 0;
    for (int i = tid; i < 4096; i += 256) c += (mask[i] != 0);
    cnt[tid] = c;
    __syncthreads();
    for (int s = 128; s; s >>= 1) {
        if (tid < s) cnt[tid] += cnt[tid + s];
        __syncthreads();
    }
    if (tid == 0) g_mask_is_u8 = (cnt[0] > 1024) ? 1 : 0;
}

// ---------------- kernel 0b: pack mask to bits ----------------
__global__ void pack_mask_kernel(const void* __restrict__ mask) {
    int idx = blockIdx.x * 256 + threadIdx.x;   // element index in 4096x4096
    int v = g_mask_is_u8 ? (int)((const unsigned char*)mask)[idx]
                         : ((const int*)mask)[idx];
    unsigned bal = __ballot_sync(0xffffffffu, v != 0);
    if ((threadIdx.x & 31) == 0) g_mbits[idx >> 5] = bal;
}

// ---------------- kernel 1: build context ----------------
__global__ void build_ctx_kernel(const float* __restrict__ feat,
                                 const float* __restrict__ reg) {
    int b = blockIdx.x;
    int x = threadIdx.x;
    if (b == 16 * C_DIM) {
        for (int c = x; c < C_DIM; c += 256) g_ctx[c] = reg[c];
        return;
    }
    int t = b / C_DIM;
    int c = b - t * C_DIM;
    float v = feat[(t * C_DIM + c) * 256 + x];
    g_ctx[(size_t)(1 + t * 256 + x) * C_DIM + c] = v;
}

// ---------------- kernel 2: fused QKV projection GEMM (fp32 -> fp16 out) ----------------
__global__ void qkv_gemm_kernel(const float* __restrict__ Wq,
                                const float* __restrict__ Wk,
                                const float* __restrict__ Wv) {
    __shared__ float sA[16][68];
    __shared__ float sB[16][68];

    int z = blockIdx.z;
    const float* W = (z == 0) ? Wq : ((z == 1) ? Wk : Wv);
    int rows = (z == 0) ? L_Q : L_CTX;
    const float* A = g_ctx + ((z == 0) ? C_DIM : 0);
    __half* out = (z == 0) ? g_q : ((z == 1) ? g_k : g_v);

    int row0 = blockIdx.x * 64;
    int n0   = blockIdx.y * 64;
    int tid = threadIdx.x;
    int ty = tid >> 4, tx = tid & 15;

    float acc[4][4] = {};
    int lam = tid >> 2;
    int lak = (tid & 3) * 4;
    int lbk = tid >> 4;
    int lbn = (tid & 15) * 4;

    for (int k0 = 0; k0 < C_DIM; k0 += 16) {
        float4 av = make_float4(0.f, 0.f, 0.f, 0.f);
        if (row0 + lam < rows)
            av = *(const float4*)&A[(size_t)(row0 + lam) * C_DIM + k0 + lak];
        sA[lak + 0][lam] = av.x;
        sA[lak + 1][lam] = av.y;
        sA[lak + 2][lam] = av.z;
        sA[lak + 3][lam] = av.w;
        *(float4*)&sB[lbk][lbn] =
            *(const float4*)&W[(size_t)(k0 + lbk) * C_DIM + n0 + lbn];
        __syncthreads();
#pragma unroll
        for (int kk = 0; kk < 16; kk++) {
            float4 a4 = *(float4*)&sA[kk][ty * 4];
            float4 b4 = *(float4*)&sB[kk][tx * 4];
            float avv[4] = {a4.x, a4.y, a4.z, a4.w};
            float bvv[4] = {b4.x, b4.y, b4.z, b4.w};
#pragma unroll
            for (int i = 0; i < 4; i++)
#pragma unroll
                for (int j = 0; j < 4; j++) acc[i][j] += avv[i] * bvv[j];
        }
        __syncthreads();
    }

    float scale = (z == 0) ? rsqrtf((float)DHEAD) : 1.0f;
#pragma unroll
    for (int i = 0; i < 4; i++) {
        int s = row0 + ty * 4 + i;
        if (s >= rows) continue;
#pragma unroll
        for (int j = 0; j < 4; j++) {
            int jc = n0 + tx * 4 + j;
            int hh = jc / DHEAD;
            int d = jc - hh * DHEAD;
            out[((size_t)hh * rows + s) * DPAD + d] = __float2half(acc[i][j] * scale);
        }
    }
}

// ---------------- kernel 3: flash attention, fp16 HMMA ----------------
// BQ=128, BK=64, 8 warps, each warp owns 16 q-rows x full key tile.
__global__ void __launch_bounds__(256) flash_kernel() {
    __shared__ __half sQ[128 * 56];
    __shared__ __half sK[64 * 56];
    __shared__ __half sV[64 * 56];

    int qb = blockIdx.x, h = blockIdx.y;
    int q0 = qb * 128;
    int tid = threadIdx.x;
    int w = tid >> 5, lane = tid & 31;
    int g = lane >> 2, qc = lane & 3;

    const __half* qg = g_q + (size_t)h * L_Q * DPAD;
    const __half* kg = g_k + (size_t)h * L_CTX * DPAD;
    const __half* vg = g_v + (size_t)h * L_CTX * DPAD;

    // fill Q tile
    for (int idx = tid; idx < 128 * 6; idx += 256) {
        int r = idx / 6, p = idx - r * 6;
        *(uint4*)&sQ[r * 56 + p * 8] =
            *(const uint4*)&qg[(size_t)(q0 + r) * DPAD + p * 8];
    }
    __syncthreads();

    // Q A-fragments (3 ksteps of 16)
    uint32_t aQ[3][4];
    uint32_t sQb = (uint32_t)__cvta_generic_to_shared(sQ);
    int wrow = w * 16;
#pragma unroll
    for (int kk = 0; kk < 3; kk++) {
        uint32_t addr = sQb +
            (uint32_t)(((wrow + (lane & 15)) * 56 + kk * 16 + ((lane >> 4) << 3)) * 2);
        ldsm4(aQ[kk], addr);
    }

    int r0 = wrow + g;
    int r1 = r0 + 8;

    // init softmax stats from register token (always visible)
    float m0 = 0.f, m1 = 0.f;
#pragma unroll
    for (int d = 0; d < DHEAD; d++) {
        float kd = __half2float(kg[d]);
        m0 += __half2float(qg[(size_t)(q0 + r0) * DPAD + d]) * kd;
        m1 += __half2float(qg[(size_t)(q0 + r1) * DPAD + d]) * kd;
    }
    float l0 = 1.f, l1 = 1.f;

    float o[5][4];
#pragma unroll
    for (int v = 0; v < 5; v++) {
        float v0 = __half2float(vg[v * 8 + qc * 2]);
        float v1 = __half2float(vg[v * 8 + qc * 2 + 1]);
        o[v][0] = v0; o[v][1] = v1; o[v][2] = v0; o[v][3] = v1;
    }

    const unsigned long long* mr0 =
        (const unsigned long long*)(g_mbits + (size_t)(q0 + r0) * 128);
    const unsigned long long* mr1 =
        (const unsigned long long*)(g_mbits + (size_t)(q0 + r1) * 128);

    uint32_t sKb = (uint32_t)__cvta_generic_to_shared(sK);
    uint32_t sVb = (uint32_t)__cvta_generic_to_shared(sV);

    for (int t = 0; t < 64; t++) {
        int k0 = t * 64;
        __syncthreads();
        // fill K,V tiles (fp16, 48 padded halfs per row)
        for (int idx = tid; idx < 64 * 6; idx += 256) {
            int r = idx / 6, p = idx - r * 6;
            size_t go = (size_t)(1 + k0 + r) * DPAD + p * 8;
            *(uint4*)&sK[r * 56 + p * 8] = *(const uint4*)&kg[go];
            *(uint4*)&sV[r * 56 + p * 8] = *(const uint4*)&vg[go];
        }
        __syncthreads();

        // ---- S = Q K^T : 8 n-tiles of 8 cols ----
        float s[8][4] = {};
#pragma unroll
        for (int kk = 0; kk < 3; kk++) {
#pragma unroll
            for (int pr = 0; pr < 4; pr++) {
                uint32_t b[4];
                uint32_t addr = sKb +
                    (uint32_t)(((pr * 16 + (lane & 15)) * 56 + kk * 16 + ((lane >> 4) << 3)) * 2);
                ldsm4(b, addr);
                uint32_t b0[2] = {b[0], b[2]};
                uint32_t b1[2] = {b[1], b[3]};
                mma16816(s[2 * pr],     aQ[kk], b0);
                mma16816(s[2 * pr + 1], aQ[kk], b1);
            }
        }

        // ---- mask + online softmax (rows fully warp-local) ----
        unsigned long long mb0 = mr0[t], mb1 = mr1[t];
        float mx0 = -1e30f, mx1 = -1e30f;
#pragma unroll
        for (int v = 0; v < 8; v++) {
            int c = v * 8 + qc * 2;
            s[v][0] = ((mb0 >> c) & 1ull)       ? s[v][0] : -1e30f;
            s[v][1] = ((mb0 >> (c + 1)) & 1ull) ? s[v][1] : -1e30f;
            s[v][2] = ((mb1 >> c) & 1ull)       ? s[v][2] : -1e30f;
            s[v][3] = ((mb1 >> (c + 1)) & 1ull) ? s[v][3] : -1e30f;
            mx0 = fmaxf(mx0, fmaxf(s[v][0], s[v][1]));
            mx1 = fmaxf(mx1, fmaxf(s[v][2], s[v][3]));
        }
        mx0 = fmaxf(mx0, __shfl_xor_sync(0xffffffffu, mx0, 1));
        mx0 = fmaxf(mx0, __shfl_xor_sync(0xffffffffu, mx0, 2));
        mx1 = fmaxf(mx1, __shfl_xor_sync(0xffffffffu, mx1, 1));
        mx1 = fmaxf(mx1, __shfl_xor_sync(0xffffffffu, mx1, 2));

        float mn0 = fmaxf(m0, mx0), mn1 = fmaxf(m1, mx1);
        float c0 = __expf(m0 - mn0), c1 = __expf(m1 - mn1);
        float sum0 = 0.f, sum1 = 0.f;
#pragma unroll
        for (int v = 0; v < 8; v++) {
            s[v][0] = __expf(s[v][0] - mn0);
            s[v][1] = __expf(s[v][1] - mn0);
            s[v][2] = __expf(s[v][2] - mn1);
            s[v][3] = __expf(s[v][3] - mn1);
            sum0 += s[v][0] + s[v][1];
            sum1 += s[v][2] + s[v][3];
        }
        sum0 += __shfl_xor_sync(0xffffffffu, sum0, 1);
        sum0 += __shfl_xor_sync(0xffffffffu, sum0, 2);
        sum1 += __shfl_xor_sync(0xffffffffu, sum1, 1);
        sum1 += __shfl_xor_sync(0xffffffffu, sum1, 2);
        l0 = l0 * c0 + sum0;
        l1 = l1 * c1 + sum1;
        m0 = mn0; m1 = mn1;

        // rescale O
#pragma unroll
        for (int v = 0; v < 5; v++) {
            o[v][0] *= c0; o[v][1] *= c0; o[v][2] *= c1; o[v][3] *= c1;
        }

        // pack P (f32 C-fragments -> fp16 A-fragments, FA2 register trick)
        uint32_t pa[4][4];
#pragma unroll
        for (int kk = 0; kk < 4; kk++) {
            int v0 = 2 * kk, v1 = 2 * kk + 1;
            pa[kk][0] = pack_half2(s[v0][0], s[v0][1]);
            pa[kk][1] = pack_half2(s[v0][2], s[v0][3]);
            pa[kk][2] = pack_half2(s[v1][0], s[v1][1]);
            pa[kk][3] = pack_half2(s[v1][2], s[v1][3]);
        }

        // ---- O += P V : 5 n-tiles (40 dims), 4 ksteps of 16 ----
#pragma unroll
        for (int kk = 0; kk < 4; kk++) {
#pragma unroll
            for (int v = 0; v < 5; v++) {
                uint32_t b[2];
                uint32_t addr = sVb +
                    (uint32_t)(((kk * 16 + (lane & 15)) * 56 + v * 8) * 2);
                ldsm2t(b, addr);
                mma16816(o[v], pa[kk], b);
            }
        }
    }

    // ---- epilogue ----
    float inv0 = 1.f / l0, inv1 = 1.f / l1;
    float* og = g_o + (size_t)q0 * C_DIM + h * DHEAD;
#pragma unroll
    for (int v = 0; v < 5; v++) {
        int n = v * 8 + qc * 2;
        *(float2*)&og[(size_t)r0 * C_DIM + n] =
            make_float2(o[v][0] * inv0, o[v][1] * inv0);
        *(float2*)&og[(size_t)r1 * C_DIM + n] =
            make_float2(o[v][2] * inv1, o[v][3] * inv1);
    }
}

// ---------------- kernel 4: output projection + bias + permute ----------------
__global__ void out_gemm_kernel(const float* __restrict__ Wo,
                                const float* __restrict__ bo,
                                float* __restrict__ out) {
    __shared__ float sA[16][68];
    __shared__ float sB[16][68];

    int row0 = blockIdx.x * 64;
    int n0   = blockIdx.y * 64;
    int tid = threadIdx.x;
    int ty = tid >> 4, tx = tid & 15;
    float acc[4][4] = {};

    int lam = tid >> 2;
    int lak = (tid & 3) * 4;
    int lbk = tid >> 4;
    int lbn = (tid & 15) * 4;

    for (int k0 = 0; k0 < C_DIM; k0 += 16) {
        float4 av = *(const float4*)&g_o[(size_t)(row0 + lam) * C_DIM + k0 + lak];
        sA[lak + 0][lam] = av.x;
        sA[lak + 1][lam] = av.y;
        sA[lak + 2][lam] = av.z;
        sA[lak + 3][lam] = av.w;
        *(float4*)&sB[lbk][lbn] =
            *(const float4*)&Wo[(size_t)(k0 + lbk) * C_DIM + n0 + lbn];
        __syncthreads();
#pragma unroll
        for (int kk = 0; kk < 16; kk++) {
            float4 a4 = *(float4*)&sA[kk][ty * 4];
            float4 b4 = *(float4*)&sB[kk][tx * 4];
            float avv[4] = {a4.x, a4.y, a4.z, a4.w};
            float bvv[4] = {b4.x, b4.y, b4.z, b4.w};
#pragma unroll
            for (int i = 0; i < 4; i++)
#pragma unroll
                for (int j = 0; j < 4; j++) acc[i][j] += avv[i] * bvv[j];
        }
        __syncthreads();
    }

#pragma unroll
    for (int i = 0; i < 4; i++) {
        int s = row0 + ty * 4 + i;
        int r = (s & 255) * 16 + (s >> 8);   // (B H W) T permutation
#pragma unroll
        for (int j = 0; j < 4; j++) {
            int c = n0 + tx * 4 + j;
            out[(size_t)r * C_DIM + c] = acc[i][j] + bo[c];
        }
    }
}

// ---------------- launch ----------------
extern "C" void kernel_launch(void* const* d_in, const int* in_sizes, int n_in,
                              void* d_out, int out_size) {
    const float* feat         = (const float*)d_in[0];
    const unsigned char* mask = (const unsigned char*)d_in[1];
    const float* Wq           = (const float*)d_in[2];
    const float* Wk           = (const float*)d_in[3];
    const float* Wv           = (const float*)d_in[4];
    const float* reg          = (const float*)d_in[5];
    const float* Wo           = (const float*)d_in[6];
    const float* bo           = (const float*)d_in[7];
    float* out                = (float*)d_out;

    (void)in_sizes; (void)n_in; (void)out_size;

    detect_mask_kernel<<<1, 256>>>(mask);
    pack_mask_kernel<<<(L_Q * 4096) / 256, 256>>>(mask);
    build_ctx_kernel<<<16 * C_DIM + 1, 256>>>(feat, reg);
    qkv_gemm_kernel<<<dim3(65, 5, 3), 256>>>(Wq, Wk, Wv);
    flash_kernel<<<dim3(32, N_HEADS), 256>>>();
    out_gemm_kernel<<<dim3(64, 5), 256>>>(Wo, bo, out);
}

// round 4
// speedup vs baseline: 4.2920x; 1.1475x over previous
#include <cuda_runtime.h>
#include <cuda_fp16.h>
#include <cstdint>

#define L_Q   4096
#define L_CTX 4097
#define C_DIM 320
#define N_HEADS 8
#define DHEAD 40
#define DPAD  48

// ---------------- device scratch (no allocations allowed) ----------------
__device__ float  g_ctx[L_CTX * C_DIM];             // context fp32
__device__ __half g_q[(size_t)N_HEADS * L_Q * DPAD];    // fp16, d 40..47 stay zero
__device__ __half g_k[(size_t)N_HEADS * L_CTX * DPAD];
__device__ __half g_v[(size_t)N_HEADS * L_CTX * DPAD];
__device__ float  g_o[L_Q * C_DIM];                 // merged-head attention output
__device__ unsigned g_mbits[L_Q * 128];             // packed mask bits
__device__ int    g_mask_is_u8;

// ---------------- mma / ldmatrix helpers ----------------
__device__ __forceinline__ void mma16816(float* d, const uint32_t* a, const uint32_t* b) {
    asm volatile(
        "mma.sync.aligned.m16n8k16.row.col.f32.f16.f16.f32 "
        "{%0,%1,%2,%3}, {%4,%5,%6,%7}, {%8,%9}, {%0,%1,%2,%3};"
        : "+f"(d[0]), "+f"(d[1]), "+f"(d[2]), "+f"(d[3])
        : "r"(a[0]), "r"(a[1]), "r"(a[2]), "r"(a[3]), "r"(b[0]), "r"(b[1]));
}
__device__ __forceinline__ void ldsm4(uint32_t* r, uint32_t saddr) {
    asm volatile("ldmatrix.sync.aligned.m8n8.x4.shared.b16 {%0,%1,%2,%3}, [%4];"
                 : "=r"(r[0]), "=r"(r[1]), "=r"(r[2]), "=r"(r[3]) : "r"(saddr));
}
__device__ __forceinline__ void ldsm2t(uint32_t* r, uint32_t saddr) {
    asm volatile("ldmatrix.sync.aligned.m8n8.x2.trans.shared.b16 {%0,%1}, [%2];"
                 : "=r"(r[0]), "=r"(r[1]) : "r"(saddr));
}
__device__ __forceinline__ uint32_t pack_half2(float lo, float hi) {
    __half2 h = __floats2half2_rn(lo, hi);
    return *(uint32_t*)&h;
}
// split a float into fp16 hi + fp16 lo(residual)
__device__ __forceinline__ void split_h(float v, __half& h, __half& l) {
    h = __float2half_rn(v);
    l = __float2half_rn(v - __half2float(h));
}

// ---------------- kernel 0: detect mask dtype ----------------
__global__ void detect_mask_kernel(const unsigned char* __restrict__ mask) {
    __shared__ int cnt[256];
    int tid = threadIdx.x;
    int c = 0;
    for (int i = tid; i < 4096; i += 256) c += (mask[i] != 0);
    cnt[tid] = c;
    __syncthreads();
    for (int s = 128; s; s >>= 1) {
        if (tid < s) cnt[tid] += cnt[tid + s];
        __syncthreads();
    }
    if (tid == 0) g_mask_is_u8 = (cnt[0] > 1024) ? 1 : 0;
}

// ---------------- kernel 0b: pack mask to bits ----------------
__global__ void pack_mask_kernel(const void* __restrict__ mask) {
    int idx = blockIdx.x * 256 + threadIdx.x;
    int v = g_mask_is_u8 ? (int)((const unsigned char*)mask)[idx]
                         : ((const int*)mask)[idx];
    unsigned bal = __ballot_sync(0xffffffffu, v != 0);
    if ((threadIdx.x & 31) == 0) g_mbits[idx >> 5] = bal;
}

// ---------------- kernel 1: build context (coalesced transpose) ----------------
// feat[t][c][x] -> g_ctx[1 + t*256 + x][c];   grid (10,8,16), block (32,8)
__global__ void build_ctx_kernel(const float* __restrict__ feat,
                                 const float* __restrict__ reg) {
    __shared__ float tile[32][33];
    int c0 = blockIdx.x * 32, x0 = blockIdx.y * 32, t = blockIdx.z;
    if (blockIdx.x == 0 && blockIdx.y == 0 && t == 0) {
        int lt = threadIdx.y * 32 + threadIdx.x;
        for (int c = lt; c < C_DIM; c += 256) g_ctx[c] = reg[c];
    }
#pragma unroll
    for (int j = 0; j < 32; j += 8)
        tile[threadIdx.y + j][threadIdx.x] =
            feat[((size_t)(t * C_DIM + c0 + threadIdx.y + j)) * 256 + x0 + threadIdx.x];
    __syncthreads();
#pragma unroll
    for (int j = 0; j < 32; j += 8)
        g_ctx[(size_t)(1 + t * 256 + x0 + threadIdx.y + j) * C_DIM + c0 + threadIdx.x] =
            tile[threadIdx.x][threadIdx.y + j];
}

// ---------------- kernel 2: fused QKV projection, split-fp16 HMMA ----------------
// grid (33, 15): x = 128-row tile, y: z=y/5 selects Q/K/V, (y%5)*64 = col tile.
__global__ void __launch_bounds__(256) qkv_hmma_kernel(const float* __restrict__ Wq,
                                                       const float* __restrict__ Wk,
                                                       const float* __restrict__ Wv) {
    __shared__ __half sAh[128 * 24], sAl[128 * 24];
    __shared__ __half sBh[16 * 72],  sBl[16 * 72];

    int by = blockIdx.y;
    int z = by / 5;
    const float* W = (z == 0) ? Wq : ((z == 1) ? Wk : Wv);
    int rows = (z == 0) ? L_Q : L_CTX;
    int ashift = (z == 0) ? 1 : 0;
    int row0 = blockIdx.x * 128;
    if (row0 >= rows) return;
    int ncol0 = (by % 5) * 64;

    int tid = threadIdx.x;
    int w = tid >> 5, lane = tid & 31;
    int g = lane >> 2, qc = lane & 3;
    int wrow = w * 16;

    uint32_t sAhb = (uint32_t)__cvta_generic_to_shared(sAh);
    uint32_t sAlb = (uint32_t)__cvta_generic_to_shared(sAl);
    uint32_t sBhb = (uint32_t)__cvta_generic_to_shared(sBh);
    uint32_t sBlb = (uint32_t)__cvta_generic_to_shared(sBl);

    float acc[8][4] = {};

    for (int k0 = 0; k0 < C_DIM; k0 += 16) {
        __syncthreads();
        // ---- A tile: 128 rows x 16 k, fp32 -> hi/lo fp16 ----
#pragma unroll
        for (int i = 0; i < 2; i++) {
            int s = tid + i * 256;
            int r = s >> 2, kq = (s & 3) << 2;
            float4 v = make_float4(0.f, 0.f, 0.f, 0.f);
            if (row0 + r < rows)
                v = *(const float4*)&g_ctx[(size_t)(row0 + r + ashift) * C_DIM + k0 + kq];
            __half hx, lx, hy, ly, hz, lz, hw, lw;
            split_h(v.x, hx, lx); split_h(v.y, hy, ly);
            split_h(v.z, hz, lz); split_h(v.w, hw, lw);
            *(__half2*)&sAh[r * 24 + kq]     = __halves2half2(hx, hy);
            *(__half2*)&sAh[r * 24 + kq + 2] = __halves2half2(hz, hw);
            *(__half2*)&sAl[r * 24 + kq]     = __halves2half2(lx, ly);
            *(__half2*)&sAl[r * 24 + kq + 2] = __halves2half2(lz, lw);
        }
        // ---- B tile: 16 k x 64 n ----
        {
            int r = tid >> 4, c4 = (tid & 15) << 2;
            float4 v = *(const float4*)&W[(size_t)(k0 + r) * C_DIM + ncol0 + c4];
            __half hx, lx, hy, ly, hz, lz, hw, lw;
            split_h(v.x, hx, lx); split_h(v.y, hy, ly);
            split_h(v.z, hz, lz); split_h(v.w, hw, lw);
            *(__half2*)&sBh[r * 72 + c4]     = __halves2half2(hx, hy);
            *(__half2*)&sBh[r * 72 + c4 + 2] = __halves2half2(hz, hw);
            *(__half2*)&sBl[r * 72 + c4]     = __halves2half2(lx, ly);
            *(__half2*)&sBl[r * 72 + c4 + 2] = __halves2half2(lz, lw);
        }
        __syncthreads();

        uint32_t ah[4], al[4];
        uint32_t aoff = (uint32_t)(((wrow + (lane & 15)) * 24 + ((lane >> 4) << 3)) * 2);
        ldsm4(ah, sAhb + aoff);
        ldsm4(al, sAlb + aoff);
#pragma unroll
        for (int nt = 0; nt < 8; nt++) {
            uint32_t bh[2], bl[2];
            uint32_t boff = (uint32_t)(((lane & 15) * 72 + nt * 8) * 2);
            ldsm2t(bh, sBhb + boff);
            ldsm2t(bl, sBlb + boff);
            mma16816(acc[nt], ah, bh);
            mma16816(acc[nt], ah, bl);
            mma16816(acc[nt], al, bh);
        }
    }

    // ---- epilogue: scale (Q only), store fp16 into [h][s][48] ----
    float scale = (z == 0) ? rsqrtf((float)DHEAD) : 1.0f;
    __half* out = (z == 0) ? g_q : ((z == 1) ? g_k : g_v);
    int r0 = row0 + wrow + g;
    int r1 = r0 + 8;
#pragma unroll
    for (int nt = 0; nt < 8; nt++) {
        int col = ncol0 + nt * 8 + qc * 2;   // even, pairs never cross head boundary
        int hh = col / DHEAD;
        int d = col - hh * DHEAD;
        if (r0 < rows) {
            out[((size_t)hh * rows + r0) * DPAD + d]     = __float2half(acc[nt][0] * scale);
            out[((size_t)hh * rows + r0) * DPAD + d + 1] = __float2half(acc[nt][1] * scale);
        }
        if (r1 < rows) {
            out[((size_t)hh * rows + r1) * DPAD + d]     = __float2half(acc[nt][2] * scale);
            out[((size_t)hh * rows + r1) * DPAD + d + 1] = __float2half(acc[nt][3] * scale);
        }
    }
}

// ---------------- kernel 3: flash attention, fp16 HMMA (unchanged) ----------------
__global__ void __launch_bounds__(256) flash_kernel() {
    __shared__ __half sQ[128 * 56];
    __shared__ __half sK[64 * 56];
    __shared__ __half sV[64 * 56];

    int qb = blockIdx.x, h = blockIdx.y;
    int q0 = qb * 128;
    int tid = threadIdx.x;
    int w = tid >> 5, lane = tid & 31;
    int g = lane >> 2, qc = lane & 3;

    const __half* qg = g_q + (size_t)h * L_Q * DPAD;
    const __half* kg = g_k + (size_t)h * L_CTX * DPAD;
    const __half* vg = g_v + (size_t)h * L_CTX * DPAD;

    for (int idx = tid; idx < 128 * 6; idx += 256) {
        int r = idx / 6, p = idx - r * 6;
        *(uint4*)&sQ[r * 56 + p * 8] =
            *(const uint4*)&qg[(size_t)(q0 + r) * DPAD + p * 8];
    }
    __syncthreads();

    uint32_t aQ[3][4];
    uint32_t sQb = (uint32_t)__cvta_generic_to_shared(sQ);
    int wrow = w * 16;
#pragma unroll
    for (int kk = 0; kk < 3; kk++) {
        uint32_t addr = sQb +
            (uint32_t)(((wrow + (lane & 15)) * 56 + kk * 16 + ((lane >> 4) << 3)) * 2);
        ldsm4(aQ[kk], addr);
    }

    int r0 = wrow + g;
    int r1 = r0 + 8;

    float m0 = 0.f, m1 = 0.f;
#pragma unroll
    for (int d = 0; d < DHEAD; d++) {
        float kd = __half2float(kg[d]);
        m0 += __half2float(qg[(size_t)(q0 + r0) * DPAD + d]) * kd;
        m1 += __half2float(qg[(size_t)(q0 + r1) * DPAD + d]) * kd;
    }
    float l0 = 1.f, l1 = 1.f;

    float o[5][4];
#pragma unroll
    for (int v = 0; v < 5; v++) {
        float v0 = __half2float(vg[v * 8 + qc * 2]);
        float v1 = __half2float(vg[v * 8 + qc * 2 + 1]);
        o[v][0] = v0; o[v][1] = v1; o[v][2] = v0; o[v][3] = v1;
    }

    const unsigned long long* mr0 =
        (const unsigned long long*)(g_mbits + (size_t)(q0 + r0) * 128);
    const unsigned long long* mr1 =
        (const unsigned long long*)(g_mbits + (size_t)(q0 + r1) * 128);

    uint32_t sKb = (uint32_t)__cvta_generic_to_shared(sK);
    uint32_t sVb = (uint32_t)__cvta_generic_to_shared(sV);

    for (int t = 0; t < 64; t++) {
        int k0 = t * 64;
        __syncthreads();
        for (int idx = tid; idx < 64 * 6; idx += 256) {
            int r = idx / 6, p = idx - r * 6;
            size_t go = (size_t)(1 + k0 + r) * DPAD + p * 8;
            *(uint4*)&sK[r * 56 + p * 8] = *(const uint4*)&kg[go];
            *(uint4*)&sV[r * 56 + p * 8] = *(const uint4*)&vg[go];
        }
        __syncthreads();

        float s[8][4] = {};
#pragma unroll
        for (int kk = 0; kk < 3; kk++) {
#pragma unroll
            for (int pr = 0; pr < 4; pr++) {
                uint32_t b[4];
                uint32_t addr = sKb +
                    (uint32_t)(((pr * 16 + (lane & 15)) * 56 + kk * 16 + ((lane >> 4) << 3)) * 2);
                ldsm4(b, addr);
                uint32_t b0[2] = {b[0], b[2]};
                uint32_t b1[2] = {b[1], b[3]};
                mma16816(s[2 * pr],     aQ[kk], b0);
                mma16816(s[2 * pr + 1], aQ[kk], b1);
            }
        }

        unsigned long long mb0 = mr0[t], mb1 = mr1[t];
        float mx0 = -1e30f, mx1 = -1e30f;
#pragma unroll
        for (int v = 0; v < 8; v++) {
            int c = v * 8 + qc * 2;
            s[v][0] = ((mb0 >> c) & 1ull)       ? s[v][0] : -1e30f;
            s[v][1] = ((mb0 >> (c + 1)) & 1ull) ? s[v][1] : -1e30f;
            s[v][2] = ((mb1 >> c) & 1ull)       ? s[v][2] : -1e30f;
            s[v][3] = ((mb1 >> (c + 1)) & 1ull) ? s[v][3] : -1e30f;
            mx0 = fmaxf(mx0, fmaxf(s[v][0], s[v][1]));
            mx1 = fmaxf(mx1, fmaxf(s[v][2], s[v][3]));
        }
        mx0 = fmaxf(mx0, __shfl_xor_sync(0xffffffffu, mx0, 1));
        mx0 = fmaxf(mx0, __shfl_xor_sync(0xffffffffu, mx0, 2));
        mx1 = fmaxf(mx1, __shfl_xor_sync(0xffffffffu, mx1, 1));
        mx1 = fmaxf(mx1, __shfl_xor_sync(0xffffffffu, mx1, 2));

        float mn0 = fmaxf(m0, mx0), mn1 = fmaxf(m1, mx1);
        float c0 = __expf(m0 - mn0), c1 = __expf(m1 - mn1);
        float sum0 = 0.f, sum1 = 0.f;
#pragma unroll
        for (int v = 0; v < 8; v++) {
            s[v][0] = __expf(s[v][0] - mn0);
            s[v][1] = __expf(s[v][1] - mn0);
            s[v][2] = __expf(s[v][2] - mn1);
            s[v][3] = __expf(s[v][3] - mn1);
            sum0 += s[v][0] + s[v][1];
            sum1 += s[v][2] + s[v][3];
        }
        sum0 += __shfl_xor_sync(0xffffffffu, sum0, 1);
        sum0 += __shfl_xor_sync(0xffffffffu, sum0, 2);
        sum1 += __shfl_xor_sync(0xffffffffu, sum1, 1);
        sum1 += __shfl_xor_sync(0xffffffffu, sum1, 2);
        l0 = l0 * c0 + sum0;
        l1 = l1 * c1 + sum1;
        m0 = mn0; m1 = mn1;

#pragma unroll
        for (int v = 0; v < 5; v++) {
            o[v][0] *= c0; o[v][1] *= c0; o[v][2] *= c1; o[v][3] *= c1;
        }

        uint32_t pa[4][4];
#pragma unroll
        for (int kk = 0; kk < 4; kk++) {
            int v0 = 2 * kk, v1 = 2 * kk + 1;
            pa[kk][0] = pack_half2(s[v0][0], s[v0][1]);
            pa[kk][1] = pack_half2(s[v0][2], s[v0][3]);
            pa[kk][2] = pack_half2(s[v1][0], s[v1][1]);
            pa[kk][3] = pack_half2(s[v1][2], s[v1][3]);
        }

#pragma unroll
        for (int kk = 0; kk < 4; kk++) {
#pragma unroll
            for (int v = 0; v < 5; v++) {
                uint32_t b[2];
                uint32_t addr = sVb +
                    (uint32_t)(((kk * 16 + (lane & 15)) * 56 + v * 8) * 2);
                ldsm2t(b, addr);
                mma16816(o[v], pa[kk], b);
            }
        }
    }

    float inv0 = 1.f / l0, inv1 = 1.f / l1;
    float* og = g_o + (size_t)q0 * C_DIM + h * DHEAD;
#pragma unroll
    for (int v = 0; v < 5; v++) {
        int n = v * 8 + qc * 2;
        *(float2*)&og[(size_t)r0 * C_DIM + n] =
            make_float2(o[v][0] * inv0, o[v][1] * inv0);
        *(float2*)&og[(size_t)r1 * C_DIM + n] =
            make_float2(o[v][2] * inv1, o[v][3] * inv1);
    }
}

// ---------------- kernel 4: output projection, split-fp16 HMMA ----------------
// grid (32, 5). A = g_o fp32 [4096][320], W = Wo, + bias, permuted rows out.
__global__ void __launch_bounds__(256) out_hmma_kernel(const float* __restrict__ Wo,
                                                       const float* __restrict__ bo,
                                                       float* __restrict__ out) {
    __shared__ __half sAh[128 * 24], sAl[128 * 24];
    __shared__ __half sBh[16 * 72],  sBl[16 * 72];

    int row0 = blockIdx.x * 128;
    int ncol0 = blockIdx.y * 64;

    int tid = threadIdx.x;
    int w = tid >> 5, lane = tid & 31;
    int g = lane >> 2, qc = lane & 3;
    int wrow = w * 16;

    uint32_t sAhb = (uint32_t)__cvta_generic_to_shared(sAh);
    uint32_t sAlb = (uint32_t)__cvta_generic_to_shared(sAl);
    uint32_t sBhb = (uint32_t)__cvta_generic_to_shared(sBh);
    uint32_t sBlb = (uint32_t)__cvta_generic_to_shared(sBl);

    float acc[8][4] = {};

    for (int k0 = 0; k0 < C_DIM; k0 += 16) {
        __syncthreads();
#pragma unroll
        for (int i = 0; i < 2; i++) {
            int s = tid + i * 256;
            int r = s >> 2, kq = (s & 3) << 2;
            float4 v = *(const float4*)&g_o[(size_t)(row0 + r) * C_DIM + k0 + kq];
            __half hx, lx, hy, ly, hz, lz, hw, lw;
            split_h(v.x, hx, lx); split_h(v.y, hy, ly);
            split_h(v.z, hz, lz); split_h(v.w, hw, lw);
            *(__half2*)&sAh[r * 24 + kq]     = __halves2half2(hx, hy);
            *(__half2*)&sAh[r * 24 + kq + 2] = __halves2half2(hz, hw);
            *(__half2*)&sAl[r * 24 + kq]     = __halves2half2(lx, ly);
            *(__half2*)&sAl[r * 24 + kq + 2] = __halves2half2(lz, lw);
        }
        {
            int r = tid >> 4, c4 = (tid & 15) << 2;
            float4 v = *(const float4*)&Wo[(size_t)(k0 + r) * C_DIM + ncol0 + c4];
            __half hx, lx, hy, ly, hz, lz, hw, lw;
            split_h(v.x, hx, lx); split_h(v.y, hy, ly);
            split_h(v.z, hz, lz); split_h(v.w, hw, lw);
            *(__half2*)&sBh[r * 72 + c4]     = __halves2half2(hx, hy);
            *(__half2*)&sBh[r * 72 + c4 + 2] = __halves2half2(hz, hw);
            *(__half2*)&sBl[r * 72 + c4]     = __halves2half2(lx, ly);
            *(__half2*)&sBl[r * 72 + c4 + 2] = __halves2half2(lz, lw);
        }
        __syncthreads();

        uint32_t ah[4], al[4];
        uint32_t aoff = (uint32_t)(((wrow + (lane & 15)) * 24 + ((lane >> 4) << 3)) * 2);
        ldsm4(ah, sAhb + aoff);
        ldsm4(al, sAlb + aoff);
#pragma unroll
        for (int nt = 0; nt < 8; nt++) {
            uint32_t bh[2], bl[2];
            uint32_t boff = (uint32_t)(((lane & 15) * 72 + nt * 8) * 2);
            ldsm2t(bh, sBhb + boff);
            ldsm2t(bl, sBlb + boff);
            mma16816(acc[nt], ah, bh);
            mma16816(acc[nt], ah, bl);
            mma16816(acc[nt], al, bh);
        }
    }

    int r0 = row0 + wrow + g;
    int r1 = r0 + 8;
    int p0 = (r0 & 255) * 16 + (r0 >> 8);   // (B H W) T permutation
    int p1 = (r1 & 255) * 16 + (r1 >> 8);
#pragma unroll
    for (int nt = 0; nt < 8; nt++) {
        int col = ncol0 + nt * 8 + qc * 2;
        float b0 = bo[col], b1 = bo[col + 1];
        *(float2*)&out[(size_t)p0 * C_DIM + col] =
            make_float2(acc[nt][0] + b0, acc[nt][1] + b1);
        *(float2*)&out[(size_t)p1 * C_DIM + col] =
            make_float2(acc[nt][2] + b0, acc[nt][3] + b1);
    }
}

// ---------------- launch ----------------
extern "C" void kernel_launch(void* const* d_in, const int* in_sizes, int n_in,
                              void* d_out, int out_size) {
    const float* feat         = (const float*)d_in[0];
    const unsigned char* mask = (const unsigned char*)d_in[1];
    const float* Wq           = (const float*)d_in[2];
    const float* Wk           = (const float*)d_in[3];
    const float* Wv           = (const float*)d_in[4];
    const float* reg          = (const float*)d_in[5];
    const float* Wo           = (const float*)d_in[6];
    const float* bo           = (const float*)d_in[7];
    float* out                = (float*)d_out;

    (void)in_sizes; (void)n_in; (void)out_size;

    detect_mask_kernel<<<1, 256>>>(mask);
    pack_mask_kernel<<<(L_Q * 4096) / 256, 256>>>(mask);
    build_ctx_kernel<<<dim3(10, 8, 16), dim3(32, 8)>>>(feat, reg);
    qkv_hmma_kernel<<<dim3(33, 15), 256>>>(Wq, Wk, Wv);
    flash_kernel<<<dim3(32, N_HEADS), 256>>>();
    out_hmma_kernel<<<dim3(32, 5), 256>>>(Wo, bo, out);
}